// round 2
// baseline (speedup 1.0000x reference)
#include <cuda_runtime.h>
#include <math.h>
#include <stdint.h>

// Problem constants (from reference): T=8192 tokens, E=8 experts, H=2048, I=5632, top_k=2
#define T_TOK   8192
#define NE      8
#define H_DIM   2048
#define I_DIM   5632
#define TOPK    2

// Pair array: 2*T real entries, each expert segment padded to 128 rows.
#define ALIGN_M   128
#define PAIR_CAP  (T_TOK * TOPK + NE * ALIGN_M)   // 17408
#define NTILES_M  (PAIR_CAP / ALIGN_M)            // 136

// ---------------- device global scratch (allocation-free) ----------------
__device__ int   g_cnt[NE];
__device__ int   g_off[NE];
__device__ int   g_cur[NE];
__device__ int   g_tok_id[T_TOK * TOPK];
__device__ float g_tok_w [T_TOK * TOPK];
__device__ int   g_pair_token [PAIR_CAP];
__device__ float g_pair_w     [PAIR_CAP];
__device__ int   g_pair_expert[PAIR_CAP];
__device__ float g_act[(size_t)PAIR_CAP * I_DIM];   // ~392 MB scratch

// ---------------- routing kernels ----------------

__global__ void init_kernel() {
    int idx = blockIdx.x * blockDim.x + threadIdx.x;
    if (idx < PAIR_CAP) {
        g_pair_token[idx]  = -1;
        g_pair_w[idx]      = 0.0f;
        g_pair_expert[idx] = 0;
    }
    if (idx < NE) g_cnt[idx] = 0;
}

__global__ void route_kernel(const float* __restrict__ logits) {
    int t = blockIdx.x * blockDim.x + threadIdx.x;
    if (t >= T_TOK) return;
    const float* lp = logits + (size_t)t * NE;
    float best = -1e30f, second = -1e30f;
    int bi = -1, si = -1;
#pragma unroll
    for (int e = 0; e < NE; ++e) {
        float v = lp[e];
        if (v > best)        { second = best; si = bi; best = v; bi = e; }
        else if (v > second) { second = v; si = e; }
    }
    // softmax over the two selected logits (best first, like jax top_k order)
    float e2 = expf(second - best);
    float denom = 1.0f + e2;
    float w0 = 1.0f / denom;
    float w1 = e2 / denom;
    g_tok_id[t * 2 + 0] = bi;  g_tok_w[t * 2 + 0] = w0;
    g_tok_id[t * 2 + 1] = si;  g_tok_w[t * 2 + 1] = w1;
    atomicAdd(&g_cnt[bi], 1);
    atomicAdd(&g_cnt[si], 1);
}

__global__ void scan_kernel() {
    if (threadIdx.x == 0 && blockIdx.x == 0) {
        int off = 0;
        for (int e = 0; e < NE; ++e) {
            g_off[e] = off;
            g_cur[e] = off;
            int c = g_cnt[e];
            off += ((c + ALIGN_M - 1) / ALIGN_M) * ALIGN_M;
        }
    }
}

__global__ void fill_kernel() {
    int t = blockIdx.x * blockDim.x + threadIdx.x;
    if (t >= T_TOK) return;
#pragma unroll
    for (int s = 0; s < TOPK; ++s) {
        int e = g_tok_id[t * 2 + s];
        float w = g_tok_w[t * 2 + s];
        int pos = atomicAdd(&g_cur[e], 1);
        g_pair_token[pos]  = t;
        g_pair_w[pos]      = w;
        g_pair_expert[pos] = e;
    }
}

// ---------------- pass 1: act = route_w * silu(X @ w1[e]^T) * (X @ w3[e]^T) ----------------
// Tile: 128 pair-rows x 64 I-cols, two B matrices share the A tile. BK = 8.
__global__ void __launch_bounds__(256) pass1_kernel(
    const float* __restrict__ hidden,
    const float* __restrict__ w1,
    const float* __restrict__ w3)
{
    __shared__ float As [8][128];
    __shared__ float B1s[8][64];
    __shared__ float B2s[8][64];

    const int m0 = blockIdx.y * 128;
    const int i0 = blockIdx.x * 64;
    const int e  = g_pair_expert[m0];
    const int tid = threadIdx.x;
    const int tx = tid & 15;        // 16 -> 64 cols (4 each)
    const int ty = tid >> 4;        // 16 -> 128 rows (8 each)

    // A load mapping: 128 rows x 8 k = 256 float4
    const int arow = tid >> 1;
    const int akq  = (tid & 1) * 4;
    const int tokenA = g_pair_token[m0 + arow];
    const float* aptr = (tokenA >= 0) ? (hidden + (size_t)tokenA * H_DIM + akq) : (const float*)0;

    // B load mapping: 64 rows x 8 k per matrix = 128 float4 each; half the CTA per matrix
    const int btid = tid & 127;
    const int brow = btid >> 1;
    const int bkq  = (btid & 1) * 4;
    const float* bbase = (tid < 128) ? w1 : w3;
    const float* bptr  = bbase + ((size_t)e * I_DIM + (i0 + brow)) * H_DIM + bkq;
    float (*Bsel)[64] = (tid < 128) ? B1s : B2s;

    float acc1[8][4];
    float acc2[8][4];
#pragma unroll
    for (int r = 0; r < 8; ++r)
#pragma unroll
        for (int c = 0; c < 4; ++c) { acc1[r][c] = 0.0f; acc2[r][c] = 0.0f; }

    for (int k0 = 0; k0 < H_DIM; k0 += 8) {
        __syncthreads();
        float4 av = make_float4(0.f, 0.f, 0.f, 0.f);
        if (aptr) av = *(const float4*)(aptr + k0);
        As[akq + 0][arow] = av.x;
        As[akq + 1][arow] = av.y;
        As[akq + 2][arow] = av.z;
        As[akq + 3][arow] = av.w;
        float4 bv = *(const float4*)(bptr + k0);
        Bsel[bkq + 0][brow] = bv.x;
        Bsel[bkq + 1][brow] = bv.y;
        Bsel[bkq + 2][brow] = bv.z;
        Bsel[bkq + 3][brow] = bv.w;
        __syncthreads();

#pragma unroll
        for (int k = 0; k < 8; ++k) {
            float a[8];
            *(float4*)(a)     = *(const float4*)(&As[k][ty * 8]);
            *(float4*)(a + 4) = *(const float4*)(&As[k][ty * 8 + 4]);
            float4 b1 = *(const float4*)(&B1s[k][tx * 4]);
            float4 b2 = *(const float4*)(&B2s[k][tx * 4]);
#pragma unroll
            for (int r = 0; r < 8; ++r) {
                acc1[r][0] += a[r] * b1.x;
                acc1[r][1] += a[r] * b1.y;
                acc1[r][2] += a[r] * b1.z;
                acc1[r][3] += a[r] * b1.w;
                acc2[r][0] += a[r] * b2.x;
                acc2[r][1] += a[r] * b2.y;
                acc2[r][2] += a[r] * b2.z;
                acc2[r][3] += a[r] * b2.w;
            }
        }
    }

    // epilogue: silu(gate) * up * route_weight -> g_act
#pragma unroll
    for (int r = 0; r < 8; ++r) {
        int m = m0 + ty * 8 + r;
        float wt = g_pair_w[m];
        float4 o;
        {
            float g = acc1[r][0], u = acc2[r][0];
            o.x = wt * u * (g / (1.0f + __expf(-g)));
        }
        {
            float g = acc1[r][1], u = acc2[r][1];
            o.y = wt * u * (g / (1.0f + __expf(-g)));
        }
        {
            float g = acc1[r][2], u = acc2[r][2];
            o.z = wt * u * (g / (1.0f + __expf(-g)));
        }
        {
            float g = acc1[r][3], u = acc2[r][3];
            o.w = wt * u * (g / (1.0f + __expf(-g)));
        }
        *(float4*)(&g_act[(size_t)m * I_DIM + i0 + tx * 4]) = o;
    }
}

// ---------------- pass 2: out[token] += act @ w2[e]^T ----------------
// Tile: 128 pair-rows x 128 H-cols, BK = 8, 8x8 per thread.
__global__ void __launch_bounds__(256) pass2_kernel(
    const float* __restrict__ w2,
    float* __restrict__ out)
{
    __shared__ float As[8][128];
    __shared__ float Bs[8][128];

    const int m0 = blockIdx.y * 128;
    const int h0 = blockIdx.x * 128;
    const int e  = g_pair_expert[m0];
    const int tid = threadIdx.x;
    const int tx = tid & 15;    // 16 -> 128 cols (8 each)
    const int ty = tid >> 4;    // 16 -> 128 rows (8 each)

    const int lrow = tid >> 1;
    const int lkq  = (tid & 1) * 4;
    const float* aptr = g_act + (size_t)(m0 + lrow) * I_DIM + lkq;
    const float* bptr = w2 + ((size_t)e * H_DIM + (h0 + lrow)) * I_DIM + lkq;

    float acc[8][8];
#pragma unroll
    for (int r = 0; r < 8; ++r)
#pragma unroll
        for (int c = 0; c < 8; ++c) acc[r][c] = 0.0f;

    for (int k0 = 0; k0 < I_DIM; k0 += 8) {
        __syncthreads();
        float4 av = *(const float4*)(aptr + k0);
        As[lkq + 0][lrow] = av.x;
        As[lkq + 1][lrow] = av.y;
        As[lkq + 2][lrow] = av.z;
        As[lkq + 3][lrow] = av.w;
        float4 bv = *(const float4*)(bptr + k0);
        Bs[lkq + 0][lrow] = bv.x;
        Bs[lkq + 1][lrow] = bv.y;
        Bs[lkq + 2][lrow] = bv.z;
        Bs[lkq + 3][lrow] = bv.w;
        __syncthreads();

#pragma unroll
        for (int k = 0; k < 8; ++k) {
            float a[8], b[8];
            *(float4*)(a)     = *(const float4*)(&As[k][ty * 8]);
            *(float4*)(a + 4) = *(const float4*)(&As[k][ty * 8 + 4]);
            *(float4*)(b)     = *(const float4*)(&Bs[k][tx * 8]);
            *(float4*)(b + 4) = *(const float4*)(&Bs[k][tx * 8 + 4]);
#pragma unroll
            for (int r = 0; r < 8; ++r)
#pragma unroll
                for (int c = 0; c < 8; ++c)
                    acc[r][c] += a[r] * b[c];
        }
    }

    // scatter-add into out (exactly 2 adds per output element across the grid)
#pragma unroll
    for (int r = 0; r < 8; ++r) {
        int token = g_pair_token[m0 + ty * 8 + r];
        if (token < 0) continue;
        float* obase = out + (size_t)token * H_DIM + h0 + tx * 8;
#pragma unroll
        for (int c = 0; c < 8; ++c)
            atomicAdd(obase + c, acc[r][c]);
    }
}

// ---------------- launch ----------------
extern "C" void kernel_launch(void* const* d_in, const int* in_sizes, int n_in,
                              void* d_out, int out_size)
{
    const float* hidden = (const float*)d_in[0];
    const float* logits = (const float*)d_in[1];
    const float* w1     = (const float*)d_in[2];
    const float* w2     = (const float*)d_in[3];
    const float* w3     = (const float*)d_in[4];
    float* out = (float*)d_out;

    cudaMemsetAsync(out, 0, (size_t)T_TOK * H_DIM * sizeof(float));

    init_kernel <<<(PAIR_CAP + 255) / 256, 256>>>();
    route_kernel<<<T_TOK / 256, 256>>>(logits);
    scan_kernel <<<1, 1>>>();
    fill_kernel <<<T_TOK / 256, 256>>>();

    pass1_kernel<<<dim3(I_DIM / 64, NTILES_M), 256>>>(hidden, w1, w3);
    pass2_kernel<<<dim3(H_DIM / 128, NTILES_M), 256>>>(w2, out);
}

// round 5
// speedup vs baseline: 1.5681x; 1.5681x over previous
#include <cuda_runtime.h>
#include <cuda_bf16.h>
#include <math.h>
#include <stdint.h>

// Problem constants: T=8192 tokens, E=8 experts, H=2048, I=5632, top_k=2
#define T_TOK   8192
#define NE      8
#define H_DIM   2048
#define I_DIM   5632
#define TOPK    2

#define ALIGN_M   128
#define PAIR_CAP  (T_TOK * TOPK + NE * ALIGN_M)   // 17408
#define NTILES_M  (PAIR_CAP / ALIGN_M)            // 136

#define HP (H_DIM / 2)   // 1024 u32 (bf16 pairs) per row
#define IP (I_DIM / 2)   // 2816

#define KBLK       32                 // k per stage = two 16-k chunks
#define STAGES     3
#define STAGE_U32  8192                // 32 KB per stage (both passes)
#define SMEM_SZ    (STAGES * STAGE_U32 * 4)   // 98304 B

// ---------------- device global scratch (allocation-free) ----------------
__device__ int   g_cnt[NE];
__device__ int   g_off[NE];
__device__ int   g_cur[NE];
__device__ int   g_tok_id[T_TOK * TOPK];
__device__ float g_tok_w [T_TOK * TOPK];
__device__ int   g_pair_token [PAIR_CAP];
__device__ float g_pair_w     [PAIR_CAP];
__device__ int   g_pair_expert[PAIR_CAP];

// bf16 hi/lo split operands, fragment-permuted pair layout
__device__ uint32_t g_hid_hi[(size_t)T_TOK * HP];
__device__ uint32_t g_hid_lo[(size_t)T_TOK * HP];
__device__ uint32_t g_w1_hi [(size_t)NE * I_DIM * HP];
__device__ uint32_t g_w1_lo [(size_t)NE * I_DIM * HP];
__device__ uint32_t g_w3_hi [(size_t)NE * I_DIM * HP];
__device__ uint32_t g_w3_lo [(size_t)NE * I_DIM * HP];
__device__ uint32_t g_w2_hi [(size_t)NE * H_DIM * IP];
__device__ uint32_t g_w2_lo [(size_t)NE * H_DIM * IP];
__device__ uint32_t g_act_hi[(size_t)PAIR_CAP * IP];
__device__ uint32_t g_act_lo[(size_t)PAIR_CAP * IP];

// ---------------- helpers ----------------
__device__ __forceinline__ uint32_t smem_u32(const void* p) {
    uint32_t a;
    asm("{ .reg .u64 t; cvta.to.shared.u64 t, %1; cvt.u32.u64 %0, t; }" : "=r"(a) : "l"(p));
    return a;
}
__device__ __forceinline__ void cp16(uint32_t dst, const void* src, uint32_t src_sz) {
    asm volatile("cp.async.cg.shared.global [%0], [%1], 16, %2;"
                 :: "r"(dst), "l"(src), "r"(src_sz) : "memory");
}
#define CP_COMMIT() asm volatile("cp.async.commit_group;" ::: "memory")
#define CP_WAIT1()  asm volatile("cp.async.wait_group 1;"  ::: "memory")

// m16n8k16 bf16 mma, fp32 accumulate. a_lo2 = {a0,a2} at row, a_hi2 = {a1,a3} at row+8.
__device__ __forceinline__ void mma_bf16(float* c, uint2 ar0, uint2 ar8, uint2 b) {
    asm volatile(
        "mma.sync.aligned.m16n8k16.row.col.f32.bf16.bf16.f32 "
        "{%0,%1,%2,%3}, {%4,%5,%6,%7}, {%8,%9}, {%0,%1,%2,%3};"
        : "+f"(c[0]), "+f"(c[1]), "+f"(c[2]), "+f"(c[3])
        : "r"(ar0.x), "r"(ar8.x), "r"(ar0.y), "r"(ar8.y), "r"(b.x), "r"(b.y));
}

__device__ __forceinline__ float silu_mul(float g, float u, float wt) {
    return wt * u * (g / (1.0f + __expf(-g)));
}
__device__ __forceinline__ uint32_t pack2(__nv_bfloat16 a, __nv_bfloat16 b) {
    return (uint32_t)__bfloat16_as_ushort(a) | ((uint32_t)__bfloat16_as_ushort(b) << 16);
}

// ---------------- routing kernels ----------------
__global__ void init_kernel() {
    int idx = blockIdx.x * blockDim.x + threadIdx.x;
    if (idx < PAIR_CAP) { g_pair_token[idx] = -1; g_pair_w[idx] = 0.0f; g_pair_expert[idx] = 0; }
    if (idx < NE) g_cnt[idx] = 0;
}

__global__ void route_kernel(const float* __restrict__ logits) {
    int t = blockIdx.x * blockDim.x + threadIdx.x;
    if (t >= T_TOK) return;
    const float* lp = logits + (size_t)t * NE;
    float best = -1e30f, second = -1e30f;
    int bi = -1, si = -1;
#pragma unroll
    for (int e = 0; e < NE; ++e) {
        float v = lp[e];
        if (v > best)        { second = best; si = bi; best = v; bi = e; }
        else if (v > second) { second = v; si = e; }
    }
    float e2 = expf(second - best);
    float denom = 1.0f + e2;
    g_tok_id[t*2+0] = bi;  g_tok_w[t*2+0] = 1.0f / denom;
    g_tok_id[t*2+1] = si;  g_tok_w[t*2+1] = e2 / denom;
    atomicAdd(&g_cnt[bi], 1);
    atomicAdd(&g_cnt[si], 1);
}

__global__ void scan_kernel() {
    if (threadIdx.x == 0 && blockIdx.x == 0) {
        int off = 0;
        for (int e = 0; e < NE; ++e) {
            g_off[e] = off; g_cur[e] = off;
            off += ((g_cnt[e] + ALIGN_M - 1) / ALIGN_M) * ALIGN_M;
        }
    }
}

__global__ void fill_kernel() {
    int t = blockIdx.x * blockDim.x + threadIdx.x;
    if (t >= T_TOK) return;
#pragma unroll
    for (int s = 0; s < TOPK; ++s) {
        int e = g_tok_id[t*2+s];
        int pos = atomicAdd(&g_cur[e], 1);
        g_pair_token[pos]  = t;
        g_pair_w[pos]      = g_tok_w[t*2+s];
        g_pair_expert[pos] = e;
    }
}

// ---------------- conversion: fp32 -> bf16 hi/lo, permuted pair layout ----------------
// Slot m within a 16-k chunk holds k-pair kp(m) = ((m&1)<<2) | (m>>1).
__global__ void convert_kernel(const float* __restrict__ src,
                               uint32_t* __restrict__ hi, uint32_t* __restrict__ lo,
                               int kdiv2) {
    int row = blockIdx.y;
    int p = blockIdx.x * 256 + threadIdx.x;   // 0..kdiv2-1
    int m = p & 7, chunk = p >> 3;
    int kp = ((m & 1) << 2) | (m >> 1);
    const float* s = src + (size_t)row * (size_t)(kdiv2 * 2) + chunk * 16 + kp * 2;
    float v0 = s[0], v1 = s[1];
    __nv_bfloat16 h0 = __float2bfloat16(v0), h1 = __float2bfloat16(v1);
    __nv_bfloat16 l0 = __float2bfloat16(v0 - __bfloat162float(h0));
    __nv_bfloat16 l1 = __float2bfloat16(v1 - __bfloat162float(h1));
    size_t o = (size_t)row * kdiv2 + p;
    hi[o] = pack2(h0, h1);
    lo[o] = pack2(l0, l1);
}

// =====================================================================
// pass 1: act = route_w * silu(X@w1^T) * (X@w3^T)   [bf16x3 emulated fp32]
// CTA: 128 thr, tile 128 pair-rows x 64 I-cols; 4 warps (2M x 2N), warp 64x32.
// Stage (u32 offsets): Ah[0] Al[2048] B1h[4096] B1l[5120] B2h[6144] B2l[7168]
//   A plane per chunk: [row128][m8]; B plane per chunk: [col64][m8]
// =====================================================================
__global__ void __launch_bounds__(128, 2) pass1_mma() {
    extern __shared__ uint32_t sm[];
    const uint32_t sb = smem_u32(sm);
    const int tid = threadIdx.x, lane = tid & 31, warp = tid >> 5;
    const int m0 = blockIdx.y * 128;
    const int i0 = blockIdx.x * 64;
    const int e  = g_pair_expert[m0];

    // staging sources
    const int tok = g_pair_token[m0 + tid];
    const uint32_t asz = (tok >= 0) ? 16u : 0u;
    const uint32_t* ah = g_hid_hi + (size_t)(tok >= 0 ? tok : 0) * HP;
    const uint32_t* al = g_hid_lo + (size_t)(tok >= 0 ? tok : 0) * HP;
    const int bcol = tid & 63, bh = tid >> 6;
    const size_t brow = ((size_t)e * I_DIM + i0 + bcol) * HP;
    const uint32_t* b1h = g_w1_hi + brow;
    const uint32_t* b1l = g_w1_lo + brow;
    const uint32_t* b2h = g_w3_hi + brow;
    const uint32_t* b2l = g_w3_lo + brow;

    const int warp_m = warp >> 1, warp_n = warp & 1;
    const int rbase = warp_m * 64 + (lane >> 2);
    const int cbase = warp_n * 32 + (lane >> 2);
    const int mo    = 2 * (lane & 3);

    float accg[4][4][4], accu[4][4][4];
#pragma unroll
    for (int fm = 0; fm < 4; ++fm)
#pragma unroll
        for (int fn = 0; fn < 4; ++fn)
#pragma unroll
            for (int x = 0; x < 4; ++x) { accg[fm][fn][x] = 0.f; accu[fm][fn][x] = 0.f; }

    const int NK = H_DIM / KBLK;   // 64

#pragma unroll 1
    for (int i = -(STAGES - 1); i < NK; ++i) {
        // issue cp.async for stage i+STAGES-1
        int ld = i + STAGES - 1;
        if (ld < NK) {
            uint32_t base = sb + (ld % STAGES) * STAGE_U32 * 4;
            int kc0 = ld * 2;   // 16-k chunk index
#pragma unroll
            for (int c = 0; c < 2; ++c) {
#pragma unroll
                for (int h = 0; h < 2; ++h) {
                    cp16(base + (((c*128 + tid)*8) + h*4) * 4,        ah  + (kc0+c)*8 + h*4, asz);
                    cp16(base + ((2048 + (c*128 + tid)*8) + h*4) * 4, al  + (kc0+c)*8 + h*4, asz);
                }
                cp16(base + ((4096 + (c*64 + bcol)*8) + bh*4) * 4, b1h + (kc0+c)*8 + bh*4, 16);
                cp16(base + ((5120 + (c*64 + bcol)*8) + bh*4) * 4, b1l + (kc0+c)*8 + bh*4, 16);
                cp16(base + ((6144 + (c*64 + bcol)*8) + bh*4) * 4, b2h + (kc0+c)*8 + bh*4, 16);
                cp16(base + ((7168 + (c*64 + bcol)*8) + bh*4) * 4, b2l + (kc0+c)*8 + bh*4, 16);
            }
        }
        CP_COMMIT();
        if (i < 0) continue;

        CP_WAIT1();
        __syncthreads();

        const uint32_t* st = sm + (i % STAGES) * STAGE_U32;
#pragma unroll
        for (int c = 0; c < 2; ++c) {
            const uint32_t* Ah = st + c * 1024;
            const uint32_t* Al = st + 2048 + c * 1024;
            uint2 ah0[4], ah8[4], al0[4], al8[4];
#pragma unroll
            for (int fm = 0; fm < 4; ++fm) {
                int rr = rbase + fm * 16;
                ah0[fm] = *(const uint2*)(Ah + rr * 8 + mo);
                ah8[fm] = *(const uint2*)(Ah + (rr + 8) * 8 + mo);
                al0[fm] = *(const uint2*)(Al + rr * 8 + mo);
                al8[fm] = *(const uint2*)(Al + (rr + 8) * 8 + mo);
            }
            const uint32_t* B1h = st + 4096 + c * 512;
            const uint32_t* B1l = st + 5120 + c * 512;
            const uint32_t* B2h = st + 6144 + c * 512;
            const uint32_t* B2l = st + 7168 + c * 512;
#pragma unroll
            for (int fn = 0; fn < 4; ++fn) {
                int cc = (cbase + fn * 8) * 8 + mo;
                uint2 v1h = *(const uint2*)(B1h + cc);
                uint2 v1l = *(const uint2*)(B1l + cc);
                uint2 v2h = *(const uint2*)(B2h + cc);
                uint2 v2l = *(const uint2*)(B2l + cc);
#pragma unroll
                for (int fm = 0; fm < 4; ++fm) {
                    mma_bf16(accg[fm][fn], ah0[fm], ah8[fm], v1h);
                    mma_bf16(accg[fm][fn], ah0[fm], ah8[fm], v1l);
                    mma_bf16(accg[fm][fn], al0[fm], al8[fm], v1h);
                    mma_bf16(accu[fm][fn], ah0[fm], ah8[fm], v2h);
                    mma_bf16(accu[fm][fn], ah0[fm], ah8[fm], v2l);
                    mma_bf16(accu[fm][fn], al0[fm], al8[fm], v2h);
                }
            }
        }
        __syncthreads();
    }

    // ---- epilogue: silu(g)*u*wt, split to bf16 hi/lo, permuted store ----
#pragma unroll
    for (int fm = 0; fm < 4; ++fm) {
        int r0 = m0 + rbase + fm * 16;
        int r1 = r0 + 8;
        float w0 = g_pair_w[r0];
        float w1_ = g_pair_w[r1];
#pragma unroll
        for (int fn = 0; fn < 4; ++fn) {
            int colg = i0 + warp_n * 32 + fn * 8 + (lane & 3) * 2;
            int chunk = colg >> 4;
            int kpin = (colg >> 1) & 7;
            int mm = 2 * (kpin & 3) + (kpin >> 2);
            size_t o0 = (size_t)r0 * IP + chunk * 8 + mm;
            size_t o1 = (size_t)r1 * IP + chunk * 8 + mm;
            float v0 = silu_mul(accg[fm][fn][0], accu[fm][fn][0], w0);
            float v1 = silu_mul(accg[fm][fn][1], accu[fm][fn][1], w0);
            float v2 = silu_mul(accg[fm][fn][2], accu[fm][fn][2], w1_);
            float v3 = silu_mul(accg[fm][fn][3], accu[fm][fn][3], w1_);
            __nv_bfloat16 h0 = __float2bfloat16(v0), h1 = __float2bfloat16(v1);
            __nv_bfloat16 h2 = __float2bfloat16(v2), h3 = __float2bfloat16(v3);
            g_act_hi[o0] = pack2(h0, h1);
            g_act_hi[o1] = pack2(h2, h3);
            g_act_lo[o0] = pack2(__float2bfloat16(v0 - __bfloat162float(h0)),
                                 __float2bfloat16(v1 - __bfloat162float(h1)));
            g_act_lo[o1] = pack2(__float2bfloat16(v2 - __bfloat162float(h2)),
                                 __float2bfloat16(v3 - __bfloat162float(h3)));
        }
    }
}

// =====================================================================
// pass 2: out[token] += act @ w2^T   [bf16x3]
// CTA: 128 thr, tile 128 pair-rows x 128 H-cols; 4 warps (2M x 2N), warp 64x64.
// Stage (u32): Ah[0] Al[2048] Bh[4096] Bl[6144]
// =====================================================================
__global__ void __launch_bounds__(128, 2) pass2_mma(float* __restrict__ out) {
    extern __shared__ uint32_t sm[];
    const uint32_t sb = smem_u32(sm);
    const int tid = threadIdx.x, lane = tid & 31, warp = tid >> 5;
    const int m0 = blockIdx.y * 128;
    const int h0 = blockIdx.x * 128;
    const int e  = g_pair_expert[m0];

    const uint32_t* ah = g_act_hi + (size_t)(m0 + tid) * IP;
    const uint32_t* al = g_act_lo + (size_t)(m0 + tid) * IP;
    const size_t brow = ((size_t)e * H_DIM + h0 + tid) * IP;
    const uint32_t* bhp = g_w2_hi + brow;
    const uint32_t* blp = g_w2_lo + brow;

    const int warp_m = warp >> 1, warp_n = warp & 1;
    const int rbase = warp_m * 64 + (lane >> 2);
    const int cbase = warp_n * 64 + (lane >> 2);
    const int mo    = 2 * (lane & 3);

    float acc[4][8][4];
#pragma unroll
    for (int fm = 0; fm < 4; ++fm)
#pragma unroll
        for (int fn = 0; fn < 8; ++fn)
#pragma unroll
            for (int x = 0; x < 4; ++x) acc[fm][fn][x] = 0.f;

    const int NK = I_DIM / KBLK;   // 176

#pragma unroll 1
    for (int i = -(STAGES - 1); i < NK; ++i) {
        int ld = i + STAGES - 1;
        if (ld < NK) {
            uint32_t base = sb + (ld % STAGES) * STAGE_U32 * 4;
            int kc0 = ld * 2;
#pragma unroll
            for (int c = 0; c < 2; ++c) {
#pragma unroll
                for (int h = 0; h < 2; ++h) {
                    cp16(base + (((c*128 + tid)*8) + h*4) * 4,        ah  + (kc0+c)*8 + h*4, 16);
                    cp16(base + ((2048 + (c*128 + tid)*8) + h*4) * 4, al  + (kc0+c)*8 + h*4, 16);
                    cp16(base + ((4096 + (c*128 + tid)*8) + h*4) * 4, bhp + (kc0+c)*8 + h*4, 16);
                    cp16(base + ((6144 + (c*128 + tid)*8) + h*4) * 4, blp + (kc0+c)*8 + h*4, 16);
                }
            }
        }
        CP_COMMIT();
        if (i < 0) continue;

        CP_WAIT1();
        __syncthreads();

        const uint32_t* st = sm + (i % STAGES) * STAGE_U32;
#pragma unroll
        for (int c = 0; c < 2; ++c) {
            const uint32_t* Ah = st + c * 1024;
            const uint32_t* Al = st + 2048 + c * 1024;
            uint2 ah0[4], ah8[4], al0[4], al8[4];
#pragma unroll
            for (int fm = 0; fm < 4; ++fm) {
                int rr = rbase + fm * 16;
                ah0[fm] = *(const uint2*)(Ah + rr * 8 + mo);
                ah8[fm] = *(const uint2*)(Ah + (rr + 8) * 8 + mo);
                al0[fm] = *(const uint2*)(Al + rr * 8 + mo);
                al8[fm] = *(const uint2*)(Al + (rr + 8) * 8 + mo);
            }
            const uint32_t* Bh = st + 4096 + c * 1024;
            const uint32_t* Bl = st + 6144 + c * 1024;
#pragma unroll
            for (int fn = 0; fn < 8; ++fn) {
                int cc = (cbase + fn * 8) * 8 + mo;
                uint2 bhv = *(const uint2*)(Bh + cc);
                uint2 blv = *(const uint2*)(Bl + cc);
#pragma unroll
                for (int fm = 0; fm < 4; ++fm) {
                    mma_bf16(acc[fm][fn], ah0[fm], ah8[fm], bhv);
                    mma_bf16(acc[fm][fn], ah0[fm], ah8[fm], blv);
                    mma_bf16(acc[fm][fn], al0[fm], al8[fm], bhv);
                }
            }
        }
        __syncthreads();
    }

    // ---- epilogue: scatter-add (exactly 2 adds per out element) ----
#pragma unroll
    for (int fm = 0; fm < 4; ++fm) {
        int r0 = m0 + rbase + fm * 16;
        int r1 = r0 + 8;
        int tok0 = g_pair_token[r0];
        int tok1 = g_pair_token[r1];
        float* o0 = (tok0 >= 0) ? out + (size_t)tok0 * H_DIM + h0 + warp_n * 64 + (lane & 3) * 2 : (float*)0;
        float* o1 = (tok1 >= 0) ? out + (size_t)tok1 * H_DIM + h0 + warp_n * 64 + (lane & 3) * 2 : (float*)0;
#pragma unroll
        for (int fn = 0; fn < 8; ++fn) {
            if (o0) {
                atomicAdd(o0 + fn * 8,     acc[fm][fn][0]);
                atomicAdd(o0 + fn * 8 + 1, acc[fm][fn][1]);
            }
            if (o1) {
                atomicAdd(o1 + fn * 8,     acc[fm][fn][2]);
                atomicAdd(o1 + fn * 8 + 1, acc[fm][fn][3]);
            }
        }
    }
}

// ---------------- launch ----------------
extern "C" void kernel_launch(void* const* d_in, const int* in_sizes, int n_in,
                              void* d_out, int out_size)
{
    const float* hidden = (const float*)d_in[0];
    const float* logits = (const float*)d_in[1];
    const float* w1     = (const float*)d_in[2];
    const float* w2     = (const float*)d_in[3];
    const float* w3     = (const float*)d_in[4];
    float* out = (float*)d_out;

    static bool attr_done = false;
    if (!attr_done) {
        cudaFuncSetAttribute(pass1_mma, cudaFuncAttributeMaxDynamicSharedMemorySize, SMEM_SZ);
        cudaFuncSetAttribute(pass2_mma, cudaFuncAttributeMaxDynamicSharedMemorySize, SMEM_SZ);
        attr_done = true;
    }

    cudaMemsetAsync(out, 0, (size_t)T_TOK * H_DIM * sizeof(float));

    init_kernel <<<(PAIR_CAP + 255) / 256, 256>>>();
    route_kernel<<<T_TOK / 256, 256>>>(logits);
    scan_kernel <<<1, 1>>>();
    fill_kernel <<<T_TOK / 256, 256>>>();

    // hi/lo bf16 conversion (permuted pair layout)
    uint32_t* hid_hi; cudaGetSymbolAddress((void**)&hid_hi, g_hid_hi);
    uint32_t* hid_lo; cudaGetSymbolAddress((void**)&hid_lo, g_hid_lo);
    uint32_t* w1_hi;  cudaGetSymbolAddress((void**)&w1_hi,  g_w1_hi);
    uint32_t* w1_lo;  cudaGetSymbolAddress((void**)&w1_lo,  g_w1_lo);
    uint32_t* w3_hi;  cudaGetSymbolAddress((void**)&w3_hi,  g_w3_hi);
    uint32_t* w3_lo;  cudaGetSymbolAddress((void**)&w3_lo,  g_w3_lo);
    uint32_t* w2_hi;  cudaGetSymbolAddress((void**)&w2_hi,  g_w2_hi);
    uint32_t* w2_lo;  cudaGetSymbolAddress((void**)&w2_lo,  g_w2_lo);

    convert_kernel<<<dim3(HP / 256, T_TOK),       256>>>(hidden, hid_hi, hid_lo, HP);
    convert_kernel<<<dim3(HP / 256, NE * I_DIM),  256>>>(w1,     w1_hi,  w1_lo,  HP);
    convert_kernel<<<dim3(HP / 256, NE * I_DIM),  256>>>(w3,     w3_hi,  w3_lo,  HP);
    convert_kernel<<<dim3(IP / 256, NE * H_DIM),  256>>>(w2,     w2_hi,  w2_lo,  IP);

    pass1_mma<<<dim3(I_DIM / 64,  NTILES_M), 128, SMEM_SZ>>>();
    pass2_mma<<<dim3(H_DIM / 128, NTILES_M), 128, SMEM_SZ>>>(out);
}

// round 6
// speedup vs baseline: 1.7198x; 1.0968x over previous
#include <cuda_runtime.h>
#include <cuda_bf16.h>
#include <math.h>
#include <stdint.h>

// Problem constants: T=8192 tokens, E=8 experts, H=2048, I=5632, top_k=2
#define T_TOK   8192
#define NE      8
#define H_DIM   2048
#define I_DIM   5632
#define TOPK    2

#define ALIGN_M   128
#define PAIR_CAP  (T_TOK * TOPK + NE * ALIGN_M)   // 17408
#define NTILES_M  (PAIR_CAP / ALIGN_M)            // 136

#define HP (H_DIM / 2)   // 1024 u32 (bf16 pairs) per row
#define IP (I_DIM / 2)   // 2816

#define KBLK       32                  // k per stage = two 16-k chunks
#define STAGES     3
#define STAGE_U32  8192                // 32 KB per stage (both passes)
#define SMEM_SZ    (STAGES * STAGE_U32 * 4)   // 98304 B

// ---------------- device global scratch (allocation-free) ----------------
__device__ int   g_off[NE];
__device__ int   g_cur[NE];
__device__ int   g_tok_id[T_TOK * TOPK];
__device__ float g_tok_w [T_TOK * TOPK];
__device__ int   g_pair_token [PAIR_CAP];
__device__ float g_pair_w     [PAIR_CAP];
__device__ int   g_pair_expert[PAIR_CAP];

// bf16 hi/lo split operands, fragment-permuted pair layout
__device__ uint32_t g_hid_hi[(size_t)T_TOK * HP];
__device__ uint32_t g_hid_lo[(size_t)T_TOK * HP];
__device__ uint32_t g_w1_hi [(size_t)NE * I_DIM * HP];
__device__ uint32_t g_w1_lo [(size_t)NE * I_DIM * HP];
__device__ uint32_t g_w3_hi [(size_t)NE * I_DIM * HP];
__device__ uint32_t g_w3_lo [(size_t)NE * I_DIM * HP];
__device__ uint32_t g_w2_hi [(size_t)NE * H_DIM * IP];
__device__ uint32_t g_w2_lo [(size_t)NE * H_DIM * IP];
__device__ uint32_t g_act_hi[(size_t)PAIR_CAP * IP];
__device__ uint32_t g_act_lo[(size_t)PAIR_CAP * IP];

// ---------------- helpers ----------------
__device__ __forceinline__ uint32_t smem_u32(const void* p) {
    uint32_t a;
    asm("{ .reg .u64 t; cvta.to.shared.u64 t, %1; cvt.u32.u64 %0, t; }" : "=r"(a) : "l"(p));
    return a;
}
__device__ __forceinline__ void cp16(uint32_t dst, const void* src, uint32_t src_sz) {
    asm volatile("cp.async.cg.shared.global [%0], [%1], 16, %2;"
                 :: "r"(dst), "l"(src), "r"(src_sz) : "memory");
}
#define CP_COMMIT() asm volatile("cp.async.commit_group;" ::: "memory")
#define CP_WAIT1()  asm volatile("cp.async.wait_group 1;"  ::: "memory")

// m16n8k16 bf16 mma, fp32 accumulate
__device__ __forceinline__ void mma_bf16(float* c, uint2 ar0, uint2 ar8, uint2 b) {
    asm volatile(
        "mma.sync.aligned.m16n8k16.row.col.f32.bf16.bf16.f32 "
        "{%0,%1,%2,%3}, {%4,%5,%6,%7}, {%8,%9}, {%0,%1,%2,%3};"
        : "+f"(c[0]), "+f"(c[1]), "+f"(c[2]), "+f"(c[3])
        : "r"(ar0.x), "r"(ar8.x), "r"(ar0.y), "r"(ar8.y), "r"(b.x), "r"(b.y));
}

__device__ __forceinline__ float silu_mul(float g, float u, float wt) {
    return wt * u * (g / (1.0f + __expf(-g)));
}
__device__ __forceinline__ uint32_t pack2(__nv_bfloat16 a, __nv_bfloat16 b) {
    return (uint32_t)__bfloat16_as_ushort(a) | ((uint32_t)__bfloat16_as_ushort(b) << 16);
}

// ---------------- conversion: fp32 -> bf16 hi/lo, permuted pair layout ----------------
__global__ void convert_kernel(const float* __restrict__ src,
                               uint32_t* __restrict__ hi, uint32_t* __restrict__ lo,
                               int kdiv2) {
    int row = blockIdx.y;
    int p = blockIdx.x * 256 + threadIdx.x;
    int m = p & 7, chunk = p >> 3;
    int kp = ((m & 1) << 2) | (m >> 1);
    const float* s = src + (size_t)row * (size_t)(kdiv2 * 2) + chunk * 16 + kp * 2;
    float v0 = s[0], v1 = s[1];
    __nv_bfloat16 h0 = __float2bfloat16(v0), h1 = __float2bfloat16(v1);
    __nv_bfloat16 l0 = __float2bfloat16(v0 - __bfloat162float(h0));
    __nv_bfloat16 l1 = __float2bfloat16(v1 - __bfloat162float(h1));
    size_t o = (size_t)row * kdiv2 + p;
    hi[o] = pack2(h0, h1);
    lo[o] = pack2(l0, l1);
}

// ---------------- routing: init + top-2 route (fused, race-free) ----------------
__global__ void init_route(const float* __restrict__ logits) {
    int idx = blockIdx.x * 256 + threadIdx.x;
    if (idx < PAIR_CAP) { g_pair_token[idx] = -1; g_pair_w[idx] = 0.0f; g_pair_expert[idx] = 0; }
    if (idx < T_TOK) {
        const float* lp = logits + (size_t)idx * NE;
        float best = -1e30f, second = -1e30f;
        int bi = -1, si = -1;
#pragma unroll
        for (int e = 0; e < NE; ++e) {
            float v = lp[e];
            if (v > best)        { second = best; si = bi; best = v; bi = e; }
            else if (v > second) { second = v; si = e; }
        }
        float e2 = expf(second - best);
        float denom = 1.0f + e2;
        g_tok_id[idx*2+0] = bi;  g_tok_w[idx*2+0] = 1.0f / denom;
        g_tok_id[idx*2+1] = si;  g_tok_w[idx*2+1] = e2 / denom;
    }
}

// ---------------- count + scan + fill (single CTA) ----------------
__global__ void scan_fill() {
    __shared__ int cnt[NE];
    const int tid = threadIdx.x;
    if (tid < NE) cnt[tid] = 0;
    __syncthreads();
    for (int t = tid; t < T_TOK; t += 1024) {
        atomicAdd(&cnt[g_tok_id[2*t]], 1);
        atomicAdd(&cnt[g_tok_id[2*t+1]], 1);
    }
    __syncthreads();
    if (tid == 0) {
        int off = 0;
        for (int e = 0; e < NE; ++e) {
            g_off[e] = off; g_cur[e] = off;
            off += ((cnt[e] + ALIGN_M - 1) / ALIGN_M) * ALIGN_M;
        }
    }
    __syncthreads();
    for (int t = tid; t < T_TOK; t += 1024) {
#pragma unroll
        for (int s = 0; s < TOPK; ++s) {
            int e = g_tok_id[t*2+s];
            int pos = atomicAdd(&g_cur[e], 1);
            g_pair_token[pos]  = t;
            g_pair_w[pos]      = g_tok_w[t*2+s];
            g_pair_expert[pos] = e;
        }
    }
}

__global__ void zero_out(float4* __restrict__ p) {
    int i = blockIdx.x * 256 + threadIdx.x;
    p[i] = make_float4(0.f, 0.f, 0.f, 0.f);
}

// =====================================================================
// pass 1: act = route_w * silu(X@w1^T) * (X@w3^T)   [bf16x3]
// CTA 128 thr, tile 128 rows x 64 I-cols; 4 warps (2M x 2N), warp 64x32.
// Stage (u32): Ah[0] Al[2048] B1h[4096] B1l[5120] B2h[6144] B2l[7168]
// =====================================================================
__global__ void __launch_bounds__(128, 2) pass1_mma() {
    extern __shared__ uint32_t sm[];
    const uint32_t sb = smem_u32(sm);
    const int tid = threadIdx.x, lane = tid & 31, warp = tid >> 5;
    const int m0 = blockIdx.y * 128;
    const int i0 = blockIdx.x * 64;
    const int e  = g_pair_expert[m0];

    const int tok = g_pair_token[m0 + tid];
    const uint32_t asz = (tok >= 0) ? 16u : 0u;
    const uint32_t* ah = g_hid_hi + (size_t)(tok >= 0 ? tok : 0) * HP;
    const uint32_t* al = g_hid_lo + (size_t)(tok >= 0 ? tok : 0) * HP;
    const int bcol = tid & 63, bh = tid >> 6;
    const size_t brow = ((size_t)e * I_DIM + i0 + bcol) * HP;
    const uint32_t* b1h = g_w1_hi + brow;
    const uint32_t* b1l = g_w1_lo + brow;
    const uint32_t* b2h = g_w3_hi + brow;
    const uint32_t* b2l = g_w3_lo + brow;

    const int warp_m = warp >> 1, warp_n = warp & 1;
    const int rbase = warp_m * 64 + (lane >> 2);
    const int cbase = warp_n * 32 + (lane >> 2);
    const int mo    = 2 * (lane & 3);

    float accg[4][4][4], accu[4][4][4];
#pragma unroll
    for (int fm = 0; fm < 4; ++fm)
#pragma unroll
        for (int fn = 0; fn < 4; ++fn)
#pragma unroll
            for (int x = 0; x < 4; ++x) { accg[fm][fn][x] = 0.f; accu[fm][fn][x] = 0.f; }

    const int NK = H_DIM / KBLK;   // 64

    // prologue: stages 0,1
#pragma unroll
    for (int s = 0; s < STAGES - 1; ++s) {
        uint32_t base = sb + s * STAGE_U32 * 4;
        int kc0 = s * 2;
#pragma unroll
        for (int c = 0; c < 2; ++c) {
#pragma unroll
            for (int h = 0; h < 2; ++h) {
                cp16(base + (((c*128 + tid)*8) + h*4) * 4,        ah + (kc0+c)*8 + h*4, asz);
                cp16(base + ((2048 + (c*128 + tid)*8) + h*4) * 4, al + (kc0+c)*8 + h*4, asz);
            }
            cp16(base + ((4096 + (c*64 + bcol)*8) + bh*4) * 4, b1h + (kc0+c)*8 + bh*4, 16);
            cp16(base + ((5120 + (c*64 + bcol)*8) + bh*4) * 4, b1l + (kc0+c)*8 + bh*4, 16);
            cp16(base + ((6144 + (c*64 + bcol)*8) + bh*4) * 4, b2h + (kc0+c)*8 + bh*4, 16);
            cp16(base + ((7168 + (c*64 + bcol)*8) + bh*4) * 4, b2l + (kc0+c)*8 + bh*4, 16);
        }
        CP_COMMIT();
    }

#pragma unroll 1
    for (int i = 0; i < NK; ++i) {
        CP_WAIT1();
        __syncthreads();

        // issue next stage AFTER the barrier (previous readers of this buffer are done)
        int ld = i + STAGES - 1;
        if (ld < NK) {
            uint32_t base = sb + (ld % STAGES) * STAGE_U32 * 4;
            int kc0 = ld * 2;
#pragma unroll
            for (int c = 0; c < 2; ++c) {
#pragma unroll
                for (int h = 0; h < 2; ++h) {
                    cp16(base + (((c*128 + tid)*8) + h*4) * 4,        ah + (kc0+c)*8 + h*4, asz);
                    cp16(base + ((2048 + (c*128 + tid)*8) + h*4) * 4, al + (kc0+c)*8 + h*4, asz);
                }
                cp16(base + ((4096 + (c*64 + bcol)*8) + bh*4) * 4, b1h + (kc0+c)*8 + bh*4, 16);
                cp16(base + ((5120 + (c*64 + bcol)*8) + bh*4) * 4, b1l + (kc0+c)*8 + bh*4, 16);
                cp16(base + ((6144 + (c*64 + bcol)*8) + bh*4) * 4, b2h + (kc0+c)*8 + bh*4, 16);
                cp16(base + ((7168 + (c*64 + bcol)*8) + bh*4) * 4, b2l + (kc0+c)*8 + bh*4, 16);
            }
        }
        CP_COMMIT();

        const uint32_t* st = sm + (i % STAGES) * STAGE_U32;
#pragma unroll
        for (int c = 0; c < 2; ++c) {
            const uint32_t* Ah  = st + c * 1024;
            const uint32_t* Al  = st + 2048 + c * 1024;
            const uint32_t* B1h = st + 4096 + c * 512;
            const uint32_t* B1l = st + 5120 + c * 512;
            const uint32_t* B2h = st + 6144 + c * 512;
            const uint32_t* B2l = st + 7168 + c * 512;

            uint2 ah0[4], ah8[4], al0[4], al8[4];
#pragma unroll
            for (int fm = 0; fm < 4; ++fm) {
                int rr = rbase + fm * 16;
                ah0[fm] = *(const uint2*)(Ah + rr * 8 + mo);
                ah8[fm] = *(const uint2*)(Ah + (rr + 8) * 8 + mo);
                al0[fm] = *(const uint2*)(Al + rr * 8 + mo);
                al8[fm] = *(const uint2*)(Al + (rr + 8) * 8 + mo);
            }
            uint2 b1hv[4], b1lv[4], b2hv[4], b2lv[4];
#pragma unroll
            for (int fn = 0; fn < 4; ++fn) {
                int cc = (cbase + fn * 8) * 8 + mo;
                b1hv[fn] = *(const uint2*)(B1h + cc);
                b1lv[fn] = *(const uint2*)(B1l + cc);
                b2hv[fn] = *(const uint2*)(B2h + cc);
                b2lv[fn] = *(const uint2*)(B2l + cc);
            }
            // 6 groups of 16 independent MMAs (same-acc reuse distance = 32)
#pragma unroll
            for (int fm = 0; fm < 4; ++fm)
#pragma unroll
                for (int fn = 0; fn < 4; ++fn) mma_bf16(accg[fm][fn], ah0[fm], ah8[fm], b1hv[fn]);
#pragma unroll
            for (int fm = 0; fm < 4; ++fm)
#pragma unroll
                for (int fn = 0; fn < 4; ++fn) mma_bf16(accu[fm][fn], ah0[fm], ah8[fm], b2hv[fn]);
#pragma unroll
            for (int fm = 0; fm < 4; ++fm)
#pragma unroll
                for (int fn = 0; fn < 4; ++fn) mma_bf16(accg[fm][fn], ah0[fm], ah8[fm], b1lv[fn]);
#pragma unroll
            for (int fm = 0; fm < 4; ++fm)
#pragma unroll
                for (int fn = 0; fn < 4; ++fn) mma_bf16(accu[fm][fn], ah0[fm], ah8[fm], b2lv[fn]);
#pragma unroll
            for (int fm = 0; fm < 4; ++fm)
#pragma unroll
                for (int fn = 0; fn < 4; ++fn) mma_bf16(accg[fm][fn], al0[fm], al8[fm], b1hv[fn]);
#pragma unroll
            for (int fm = 0; fm < 4; ++fm)
#pragma unroll
                for (int fn = 0; fn < 4; ++fn) mma_bf16(accu[fm][fn], al0[fm], al8[fm], b2hv[fn]);
        }
    }

    // ---- epilogue ----
#pragma unroll
    for (int fm = 0; fm < 4; ++fm) {
        int r0 = m0 + rbase + fm * 16;
        int r1 = r0 + 8;
        float w0 = g_pair_w[r0];
        float w1_ = g_pair_w[r1];
#pragma unroll
        for (int fn = 0; fn < 4; ++fn) {
            int colg = i0 + warp_n * 32 + fn * 8 + (lane & 3) * 2;
            int chunk = colg >> 4;
            int kpin = (colg >> 1) & 7;
            int mm = 2 * (kpin & 3) + (kpin >> 2);
            size_t o0 = (size_t)r0 * IP + chunk * 8 + mm;
            size_t o1 = (size_t)r1 * IP + chunk * 8 + mm;
            float v0 = silu_mul(accg[fm][fn][0], accu[fm][fn][0], w0);
            float v1 = silu_mul(accg[fm][fn][1], accu[fm][fn][1], w0);
            float v2 = silu_mul(accg[fm][fn][2], accu[fm][fn][2], w1_);
            float v3 = silu_mul(accg[fm][fn][3], accu[fm][fn][3], w1_);
            __nv_bfloat16 h0 = __float2bfloat16(v0), h1 = __float2bfloat16(v1);
            __nv_bfloat16 h2 = __float2bfloat16(v2), h3 = __float2bfloat16(v3);
            g_act_hi[o0] = pack2(h0, h1);
            g_act_hi[o1] = pack2(h2, h3);
            g_act_lo[o0] = pack2(__float2bfloat16(v0 - __bfloat162float(h0)),
                                 __float2bfloat16(v1 - __bfloat162float(h1)));
            g_act_lo[o1] = pack2(__float2bfloat16(v2 - __bfloat162float(h2)),
                                 __float2bfloat16(v3 - __bfloat162float(h3)));
        }
    }
}

// =====================================================================
// pass 2: out[token] += act @ w2^T   [bf16x3]
// CTA 128 thr, tile 128 rows x 128 H-cols; 4 warps (2M x 2N), warp 64x64.
// Stage (u32): Ah[0] Al[2048] Bh[4096] Bl[6144]
// =====================================================================
__global__ void __launch_bounds__(128, 2) pass2_mma(float* __restrict__ out) {
    extern __shared__ uint32_t sm[];
    const uint32_t sb = smem_u32(sm);
    const int tid = threadIdx.x, lane = tid & 31, warp = tid >> 5;
    const int m0 = blockIdx.y * 128;
    const int h0 = blockIdx.x * 128;
    const int e  = g_pair_expert[m0];

    const uint32_t* ah = g_act_hi + (size_t)(m0 + tid) * IP;
    const uint32_t* al = g_act_lo + (size_t)(m0 + tid) * IP;
    const size_t brow = ((size_t)e * H_DIM + h0 + tid) * IP;
    const uint32_t* bhp = g_w2_hi + brow;
    const uint32_t* blp = g_w2_lo + brow;

    const int warp_m = warp >> 1, warp_n = warp & 1;
    const int rbase = warp_m * 64 + (lane >> 2);
    const int cbase = warp_n * 64 + (lane >> 2);
    const int mo    = 2 * (lane & 3);

    float acc[4][8][4];
#pragma unroll
    for (int fm = 0; fm < 4; ++fm)
#pragma unroll
        for (int fn = 0; fn < 8; ++fn)
#pragma unroll
            for (int x = 0; x < 4; ++x) acc[fm][fn][x] = 0.f;

    const int NK = I_DIM / KBLK;   // 176

#pragma unroll
    for (int s = 0; s < STAGES - 1; ++s) {
        uint32_t base = sb + s * STAGE_U32 * 4;
        int kc0 = s * 2;
#pragma unroll
        for (int c = 0; c < 2; ++c)
#pragma unroll
            for (int h = 0; h < 2; ++h) {
                cp16(base + (((c*128 + tid)*8) + h*4) * 4,        ah  + (kc0+c)*8 + h*4, 16);
                cp16(base + ((2048 + (c*128 + tid)*8) + h*4) * 4, al  + (kc0+c)*8 + h*4, 16);
                cp16(base + ((4096 + (c*128 + tid)*8) + h*4) * 4, bhp + (kc0+c)*8 + h*4, 16);
                cp16(base + ((6144 + (c*128 + tid)*8) + h*4) * 4, blp + (kc0+c)*8 + h*4, 16);
            }
        CP_COMMIT();
    }

#pragma unroll 1
    for (int i = 0; i < NK; ++i) {
        CP_WAIT1();
        __syncthreads();

        int ld = i + STAGES - 1;
        if (ld < NK) {
            uint32_t base = sb + (ld % STAGES) * STAGE_U32 * 4;
            int kc0 = ld * 2;
#pragma unroll
            for (int c = 0; c < 2; ++c)
#pragma unroll
                for (int h = 0; h < 2; ++h) {
                    cp16(base + (((c*128 + tid)*8) + h*4) * 4,        ah  + (kc0+c)*8 + h*4, 16);
                    cp16(base + ((2048 + (c*128 + tid)*8) + h*4) * 4, al  + (kc0+c)*8 + h*4, 16);
                    cp16(base + ((4096 + (c*128 + tid)*8) + h*4) * 4, bhp + (kc0+c)*8 + h*4, 16);
                    cp16(base + ((6144 + (c*128 + tid)*8) + h*4) * 4, blp + (kc0+c)*8 + h*4, 16);
                }
        }
        CP_COMMIT();

        const uint32_t* st = sm + (i % STAGES) * STAGE_U32;
#pragma unroll
        for (int c = 0; c < 2; ++c) {
            const uint32_t* Ah = st + c * 1024;
            const uint32_t* Al = st + 2048 + c * 1024;
            const uint32_t* Bh = st + 4096 + c * 1024;
            const uint32_t* Bl = st + 6144 + c * 1024;

            uint2 ah0[4], ah8[4], al0[4], al8[4];
#pragma unroll
            for (int fm = 0; fm < 4; ++fm) {
                int rr = rbase + fm * 16;
                ah0[fm] = *(const uint2*)(Ah + rr * 8 + mo);
                ah8[fm] = *(const uint2*)(Ah + (rr + 8) * 8 + mo);
                al0[fm] = *(const uint2*)(Al + rr * 8 + mo);
                al8[fm] = *(const uint2*)(Al + (rr + 8) * 8 + mo);
            }
            uint2 bhv[8], blv[8];
#pragma unroll
            for (int fn = 0; fn < 8; ++fn) {
                int cc = (cbase + fn * 8) * 8 + mo;
                bhv[fn] = *(const uint2*)(Bh + cc);
                blv[fn] = *(const uint2*)(Bl + cc);
            }
            // 3 groups of 32 independent MMAs
#pragma unroll
            for (int fm = 0; fm < 4; ++fm)
#pragma unroll
                for (int fn = 0; fn < 8; ++fn) mma_bf16(acc[fm][fn], ah0[fm], ah8[fm], bhv[fn]);
#pragma unroll
            for (int fm = 0; fm < 4; ++fm)
#pragma unroll
                for (int fn = 0; fn < 8; ++fn) mma_bf16(acc[fm][fn], ah0[fm], ah8[fm], blv[fn]);
#pragma unroll
            for (int fm = 0; fm < 4; ++fm)
#pragma unroll
                for (int fn = 0; fn < 8; ++fn) mma_bf16(acc[fm][fn], al0[fm], al8[fm], bhv[fn]);
        }
    }

    // ---- epilogue: scatter-add ----
#pragma unroll
    for (int fm = 0; fm < 4; ++fm) {
        int r0 = m0 + rbase + fm * 16;
        int r1 = r0 + 8;
        int tok0 = g_pair_token[r0];
        int tok1 = g_pair_token[r1];
        float* o0 = (tok0 >= 0) ? out + (size_t)tok0 * H_DIM + h0 + warp_n * 64 + (lane & 3) * 2 : (float*)0;
        float* o1 = (tok1 >= 0) ? out + (size_t)tok1 * H_DIM + h0 + warp_n * 64 + (lane & 3) * 2 : (float*)0;
#pragma unroll
        for (int fn = 0; fn < 8; ++fn) {
            if (o0) {
                atomicAdd(o0 + fn * 8,     acc[fm][fn][0]);
                atomicAdd(o0 + fn * 8 + 1, acc[fm][fn][1]);
            }
            if (o1) {
                atomicAdd(o1 + fn * 8,     acc[fm][fn][2]);
                atomicAdd(o1 + fn * 8 + 1, acc[fm][fn][3]);
            }
        }
    }
}

// ---------------- launch ----------------
extern "C" void kernel_launch(void* const* d_in, const int* in_sizes, int n_in,
                              void* d_out, int out_size)
{
    const float* hidden = (const float*)d_in[0];
    const float* logits = (const float*)d_in[1];
    const float* w1     = (const float*)d_in[2];
    const float* w2     = (const float*)d_in[3];
    const float* w3     = (const float*)d_in[4];
    float* out = (float*)d_out;

    static bool attr_done = false;
    if (!attr_done) {
        cudaFuncSetAttribute(pass1_mma, cudaFuncAttributeMaxDynamicSharedMemorySize, SMEM_SZ);
        cudaFuncSetAttribute(pass2_mma, cudaFuncAttributeMaxDynamicSharedMemorySize, SMEM_SZ);
        attr_done = true;
    }

    uint32_t* hid_hi; cudaGetSymbolAddress((void**)&hid_hi, g_hid_hi);
    uint32_t* hid_lo; cudaGetSymbolAddress((void**)&hid_lo, g_hid_lo);
    uint32_t* w1_hi;  cudaGetSymbolAddress((void**)&w1_hi,  g_w1_hi);
    uint32_t* w1_lo;  cudaGetSymbolAddress((void**)&w1_lo,  g_w1_lo);
    uint32_t* w3_hi;  cudaGetSymbolAddress((void**)&w3_hi,  g_w3_hi);
    uint32_t* w3_lo;  cudaGetSymbolAddress((void**)&w3_lo,  g_w3_lo);
    uint32_t* w2_hi;  cudaGetSymbolAddress((void**)&w2_hi,  g_w2_hi);
    uint32_t* w2_lo;  cudaGetSymbolAddress((void**)&w2_lo,  g_w2_lo);

    // launches 1-5
    convert_kernel<<<dim3(HP / 256, T_TOK),      256>>>(hidden, hid_hi, hid_lo, HP);
    convert_kernel<<<dim3(HP / 256, NE * I_DIM), 256>>>(w1,     w1_hi,  w1_lo,  HP);
    convert_kernel<<<dim3(HP / 256, NE * I_DIM), 256>>>(w3,     w3_hi,  w3_lo,  HP);
    init_route<<<(PAIR_CAP + 255) / 256, 256>>>(logits);
    scan_fill<<<1, 1024>>>();

    // launch 6: pass1 (ncu -s 5 -c 1 profiles this one)
    pass1_mma<<<dim3(I_DIM / 64, NTILES_M), 128, SMEM_SZ>>>();

    convert_kernel<<<dim3(IP / 256, NE * H_DIM), 256>>>(w2, w2_hi, w2_lo, IP);
    zero_out<<<(T_TOK * H_DIM / 4) / 256, 256>>>((float4*)out);

    pass2_mma<<<dim3(H_DIM / 128, NTILES_M), 128, SMEM_SZ>>>(out);
}